// round 17
// baseline (speedup 1.0000x reference)
#include <cuda_runtime.h>
#include <cuda_bf16.h>
#include <math.h>
#include <stdint.h>

typedef unsigned long long u64;

#define TPB 256
#define OUT_GATE_BASE 33554432UL   // B*M*D

#if defined(__CUDA_ARCH_FEAT_SM103_ALL) || \
    (defined(__CUDA_ARCH_SPECIFIC__) && (__CUDA_ARCH_SPECIFIC__ == 1030)) || \
    (defined(__CUDA_ARCH_FAMILY_SPECIFIC__) && (__CUDA_ARCH_FAMILY_SPECIFIC__ == 1030))
#define GB_TC 1
#else
#define GB_TC 0
#endif

// scratch
__device__ float g_y [32768u * 4u * 256u];                // 128MB
__device__ float g_oh[4u * 32768u * 256u];                // 128MB  Oh[m][b][256]
__device__ float g_ao[4u * 32768u * 256u];                // fallback only
__device__ __nv_bfloat16 g_w1t[64u * 32768u];             // FF1 tiles (hi|lo)
__device__ __nv_bfloat16 g_w2t[64u * 32768u];             // FF2 tiles
__device__ __nv_bfloat16 g_wkt[32u * 16384u];             // Wk tiles 128n x 64k (hi|lo)
__device__ __nv_bfloat16 g_wvt[32u * 16384u];             // Wv tiles
__device__ __nv_bfloat16 g_wqt[16u * 32768u];             // Wq tiles 256n x 64k (scaled)
__device__ __nv_bfloat16 g_wot[16u * 32768u];             // Wo tiles 256n x 64k
__device__ __nv_bfloat16 g_wct[16u * 8192u];              // Wc = Wo^T·g1w_ao tiles 64n x 64k
__device__ __nv_bfloat16 g_wxt[16u * 8192u];              // g1w_x tiles 64n x 64k
__device__ float g_bc[256];                               // bc[m][64] = bo·g1w_ao + g1b
__device__ unsigned g_hfscr[1024u * 131072u];             // hf scratch

// ---------- helpers ----------
static __device__ __forceinline__ unsigned pk2(__nv_bfloat16 a, __nv_bfloat16 b) {
    return (unsigned)__bfloat16_as_ushort(a) | ((unsigned)__bfloat16_as_ushort(b) << 16);
}
static __device__ __forceinline__ void bsplit(float v, __nv_bfloat16& h, __nv_bfloat16& l) {
    h = __float2bfloat16(v);
    l = __float2bfloat16(v - __bfloat162float(h));
}
static __device__ __forceinline__ uint32_t swz128(uint32_t b) { return b ^ ((b >> 3) & 0x70); }
static __device__ __forceinline__ uint32_t smem_to_u32(const void* p) {
    uint32_t a;
    asm("{ .reg .u64 t; cvta.to.shared.u64 t, %1; cvt.u32.u64 %0, t; }" : "=r"(a) : "l"(p));
    return a;
}

// reconstruct a weight element from 128n x 64k split tiles (fallback only)
static __device__ __forceinline__ float wrec128(const __nv_bfloat16* wt, int m, int n, int k) {
    const int nch = n >> 7, nn = n & 127, kch = k >> 6, kk = k & 63;
    const __nv_bfloat16* tb = wt + (size_t)(((m * 2 + nch) * 4 + kch)) * 16384;
    const uint32_t sw = swz128((uint32_t)(nn >> 3) * 1024 + (nn & 7) * 128 + kk * 2);
    return __bfloat162float(tb[sw >> 1]) + __bfloat162float(tb[8192 + (sw >> 1)]);
}
// reconstruct from 256n x 64k split tiles (fallback only)
static __device__ __forceinline__ float wrec256(const __nv_bfloat16* wt, int m, int n, int k) {
    const int kch = k >> 6, kk = k & 63;
    const __nv_bfloat16* tb = wt + (size_t)(m * 4 + kch) * 32768;
    const uint32_t sw = swz128((uint32_t)(n >> 3) * 1024 + (n & 7) * 128 + kk * 2);
    return __bfloat162float(tb[sw >> 1]) + __bfloat162float(tb[16384 + (sw >> 1)]);
}

#if GB_TC
// ---------- tcgen05 ----------
static __device__ __forceinline__ uint32_t elect_one_pred() {
    uint32_t pred;
    asm volatile(
        "{\n\t.reg .pred p;\n\telect.sync _|p, 0xFFFFFFFF;\n\tselp.b32 %0, 1, 0, p;\n\t}"
        : "=r"(pred));
    return pred;
}
#define TCGEN05_ALLOC(sa, n) \
    asm volatile("tcgen05.alloc.cta_group::1.sync.aligned.shared::cta.b32 [%0], %1;" \
                 :: "r"((uint32_t)(sa)), "r"((uint32_t)(n)) : "memory")
#define TCGEN05_DEALLOC(ta, n) \
    asm volatile("tcgen05.dealloc.cta_group::1.sync.aligned.b32 %0, %1;" :: "r"(ta), "r"((uint32_t)(n)))
#define TCGEN05_COMMIT(mb) \
    asm volatile("tcgen05.commit.cta_group::1.mbarrier::arrive::one.shared::cluster.b64 [%0];" \
                 :: "r"((uint32_t)(mb)) : "memory")
#define TCGEN05_WAIT_LD()  asm volatile("tcgen05.wait::ld.sync.aligned;" ::: "memory")
#define TCGEN05_FENCE_AFTER()  asm volatile("tcgen05.fence::after_thread_sync;" ::: "memory")
#define TCGEN05_FENCE_BEFORE() asm volatile("tcgen05.fence::before_thread_sync;" ::: "memory")
#define MBARRIER_INIT(mb, c) \
    asm volatile("mbarrier.init.shared.b64 [%0], %1;" :: "r"((uint32_t)(mb)), "r"((uint32_t)(c)) : "memory")
#define MBARRIER_WAIT_PARITY(mb, par) do { \
    uint32_t _mb = (uint32_t)(mb), _pa = (uint32_t)(par), _dn; \
    asm volatile("{\n\t.reg .pred p;\n\t" \
        "mbarrier.try_wait.parity.acquire.cta.shared::cta.b64 p, [%1], %2;\n\t" \
        "selp.b32 %0, 1, 0, p;\n\t}" : "=r"(_dn) : "r"(_mb), "r"(_pa) : "memory"); \
    if (!_dn) { \
        asm volatile("{\n\t.reg .pred P1;\n\t" \
            "WL_%=:\n\tmbarrier.try_wait.parity.acquire.cta.shared::cta.b64 P1, [%0], %1, 0x989680;\n\t" \
            "@P1 bra.uni WD_%=;\n\tbra.uni WL_%=;\n\tWD_%=:\n\t}" \
            :: "r"(_mb), "r"(_pa) : "memory"); \
    } \
} while (0)
#define TCGEN05_LD_32X32B_X32(r, ta) \
    asm volatile("tcgen05.ld.sync.aligned.32x32b.x32.b32 " \
        "{%0, %1, %2, %3, %4, %5, %6, %7, %8, %9, %10, %11, %12, %13, %14, %15, " \
        "%16, %17, %18, %19, %20, %21, %22, %23, %24, %25, %26, %27, %28, %29, %30, %31}, [%32];" \
        : "=r"((r)[0]),  "=r"((r)[1]),  "=r"((r)[2]),  "=r"((r)[3]), \
          "=r"((r)[4]),  "=r"((r)[5]),  "=r"((r)[6]),  "=r"((r)[7]), \
          "=r"((r)[8]),  "=r"((r)[9]),  "=r"((r)[10]), "=r"((r)[11]), \
          "=r"((r)[12]), "=r"((r)[13]), "=r"((r)[14]), "=r"((r)[15]), \
          "=r"((r)[16]), "=r"((r)[17]), "=r"((r)[18]), "=r"((r)[19]), \
          "=r"((r)[20]), "=r"((r)[21]), "=r"((r)[22]), "=r"((r)[23]), \
          "=r"((r)[24]), "=r"((r)[25]), "=r"((r)[26]), "=r"((r)[27]), \
          "=r"((r)[28]), "=r"((r)[29]), "=r"((r)[30]), "=r"((r)[31]) \
        : "r"(ta))

static constexpr u64 SMEM_DESC_BASE_SW128 =
    (u64(2) << 61) | (u64(1) << 46) | (u64(64) << 32) | (u64(1) << 16);
#define MAKE_SMEM_DESC(a) (SMEM_DESC_BASE_SW128 | ((u64)((a) >> 4) & 0x3FFF))

static __device__ __forceinline__ void mma_f16_ss(uint32_t d, u64 ad, u64 bd,
                                                  uint32_t idesc, uint32_t en) {
    asm volatile(
        "{\n\t.reg .pred p;\n\tsetp.ne.u32 p, %4, 0;\n\t"
        "tcgen05.mma.cta_group::1.kind::f16 [%0], %1, %2, %3, {%5, %5, %5, %5}, p;\n\t}"
        :: "r"(d), "l"(ad), "l"(bd), "r"(idesc), "r"(en), "r"(0u)
        : "memory");
}
#endif  // GB_TC

#define IDESC_BF16_M128_N128 0x8200490u
#define IDESC_BF16_M128_N256 0x8400490u
#define IDESC_BF16_M128_N64  0x8100490u

// =====================================================================
// Kernel 0: pre-split + pre-swizzle weights (f1,f2,Wk,Wv,Wq,Wo)
// =====================================================================
__global__ __launch_bounds__(256, 4)
void conv_w_kernel(const float* __restrict__ f1w, const float* __restrict__ f2w,
                   const float* __restrict__ Wk, const float* __restrict__ Wv,
                   const float* __restrict__ Wq, const float* __restrict__ Wo)
{
    const unsigned gidx = blockIdx.x * 256 + threadIdx.x;
    if (gidx < 2097152u) {
        const int arr = gidx >> 20;
        const unsigned rem = gidx & 0xFFFFFu;
        const int t = rem >> 14;
        const int e = rem & 16383;
        const int n = e >> 6, k = e & 63;
        const int m = t >> 4, c1 = (t >> 2) & 3, c2 = t & 3;
        float w;
        if (arr == 0)
            w = f1w[(size_t)m * 262144 + (size_t)(c1 * 256 + n) * 256 + c2 * 64 + k];
        else
            w = f2w[(size_t)m * 262144 + (size_t)n * 1024 + c1 * 256 + c2 * 64 + k];
        __nv_bfloat16 h, l;
        bsplit(w, h, l);
        const uint32_t sw = swz128((uint32_t)(n >> 3) * 1024 + (n & 7) * 128 + k * 2);
        __nv_bfloat16* dst = (arr == 0 ? g_w1t : g_w2t) + (size_t)t * 32768;
        dst[sw >> 1]           = h;
        dst[16384 + (sw >> 1)] = l;
    } else if (gidx < 2621440u) {
        const unsigned idx2 = gidx - 2097152u;
        const int arr2 = idx2 >> 18;
        const unsigned rem = idx2 & 0x3FFFFu;
        const int t = rem >> 13;
        const int e = rem & 8191;
        const int n = e >> 6, k = e & 63;
        const int m = t >> 3, nch = (t >> 2) & 1, kch = t & 3;
        const float* W = (arr2 == 0 ? Wk : Wv);
        const float w = W[(size_t)m * 65536 + (size_t)(nch * 128 + n) * 256 + kch * 64 + k];
        __nv_bfloat16 h, l;
        bsplit(w, h, l);
        const uint32_t sw = swz128((uint32_t)(n >> 3) * 1024 + (n & 7) * 128 + k * 2);
        __nv_bfloat16* dst = (arr2 == 0 ? g_wkt : g_wvt) + (size_t)t * 16384;
        dst[sw >> 1]          = h;
        dst[8192 + (sw >> 1)] = l;
    } else {
        const unsigned idx3 = gidx - 2621440u;
        const int arr3 = idx3 >> 18;
        const unsigned rem = idx3 & 0x3FFFFu;
        const int t = rem >> 14;
        const int e = rem & 16383;
        const int n = e >> 6, k = e & 63;
        const int m = t >> 2, kch = t & 3;
        const float* W = (arr3 == 0 ? Wq : Wo);
        float w = W[(size_t)m * 65536 + (size_t)n * 256 + kch * 64 + k];
        if (arr3 == 0) w *= 0.17677669529663687f;
        __nv_bfloat16 h, l;
        bsplit(w, h, l);
        const uint32_t sw = swz128((uint32_t)(n >> 3) * 1024 + (n & 7) * 128 + k * 2);
        __nv_bfloat16* dst = (arr3 == 0 ? g_wqt : g_wot) + (size_t)t * 32768;
        dst[sw >> 1]           = h;
        dst[16384 + (sw >> 1)] = l;
    }
}

// =====================================================================
// Kernel 0b: Wc = Wo^T·g1w_ao, bc = bo·g1w_ao + g1b, + split g1w_x tiles
// grid 16: (m, dch)
// =====================================================================
__global__ __launch_bounds__(256, 4)
void gcma_wc(const float* __restrict__ Wo, const float* __restrict__ bo,
             const float* __restrict__ g1w, const float* __restrict__ g1b)
{
    const int m = blockIdx.x >> 2, dch = blockIdx.x & 3;
    const int tid = threadIdx.x;
    // Wc for d in [dch*64,+64), h in [0,64)
    for (int e = tid; e < 4096; e += 256) {
        const int dd = e >> 6, h = e & 63;
        const int d = dch * 64 + dd;
        float s = 0.f;
        for (int o = 0; o < 256; ++o)
            s += Wo[(size_t)m * 65536 + (size_t)o * 256 + d] *
                 g1w[(size_t)m * 32768 + (size_t)h * 512 + 256 + o];
        __nv_bfloat16 hh, ll;
        bsplit(s, hh, ll);
        const uint32_t sw = swz128((uint32_t)(h >> 3) * 1024 + (h & 7) * 128 + dd * 2);
        __nv_bfloat16* dst = g_wct + (size_t)(m * 4 + dch) * 8192;
        dst[sw >> 1]          = hh;
        dst[4096 + (sw >> 1)] = ll;
    }
    // g1w_x tiles: k in [dch*64,+64), h in [0,64)
    for (int e = tid; e < 4096; e += 256) {
        const int kk = e >> 6, h = e & 63;
        const float w = g1w[(size_t)m * 32768 + (size_t)h * 512 + dch * 64 + kk];
        __nv_bfloat16 hh, ll;
        bsplit(w, hh, ll);
        const uint32_t sw = swz128((uint32_t)(h >> 3) * 1024 + (h & 7) * 128 + kk * 2);
        __nv_bfloat16* dst = g_wxt + (size_t)(m * 4 + dch) * 8192;
        dst[sw >> 1]          = hh;
        dst[4096 + (sw >> 1)] = ll;
    }
    if (dch == 0 && tid < 64) {
        float s = g1b[m * 64 + tid];
        for (int o = 0; o < 256; ++o)
            s += bo[m * 256 + o] * g1w[(size_t)m * 32768 + (size_t)tid * 512 + 256 + o];
        g_bc[m * 64 + tid] = s;
    }
}

// =====================================================================
// shared smem layout: header | A 128KB | 4 x 16KB B buffers
// =====================================================================
#define KV_SMEM 197632
#define KV_MB0  16
#define KV_MB1  24
#define KV_GATE 128      // 128 floats (512B), within header
#define KV_AHI  1024
#define KV_ALO  66560
#define KV_B0H  132096
#define KV_B0L  148480
#define KV_B1H  164864
#define KV_B1L  181248

// =====================================================================
// Kernel A: fused Q,K,V projection + attention. grid 1024, 256 threads.
// =====================================================================
__global__ __launch_bounds__(256, 1)
void gcma_kvattn(const float* __restrict__ x,
                 const float* __restrict__ bq,
                 const float* __restrict__ bk, const float* __restrict__ bv)
{
    extern __shared__ char smA[];
    const int tid = threadIdx.x;
    const int r0  = blockIdx.x * 128;

#if GB_TC
    const uint32_t sbase = smem_to_u32(smA);
    const int wid = tid >> 5, lane = tid & 31;
    char* sAhi = smA + KV_AHI;
    char* sAlo = smA + KV_ALO;

    if (wid == 0) TCGEN05_ALLOC(sbase + 0, 512);
    if (tid == 0) { MBARRIER_INIT(sbase + KV_MB0, 1); MBARRIER_INIT(sbase + KV_MB1, 1); }
    __syncthreads();
    uint32_t tmem;
    asm volatile("ld.shared.b32 %0, [%1];" : "=r"(tmem) : "r"(sbase + 0));

    for (int idx = tid; idx < 8192; idx += 256) {
        const int r = idx >> 6, k = (idx & 63) << 2;
        const float4 v = *reinterpret_cast<const float4*>(x + (size_t)(r0 + r) * 256 + k);
        __nv_bfloat16 h0, h1, h2, h3, l0, l1, l2, l3;
        bsplit(v.x, h0, l0); bsplit(v.y, h1, l1);
        bsplit(v.z, h2, l2); bsplit(v.w, h3, l3);
        const uint32_t sw = swz128((uint32_t)((r >> 3) + (k >> 6) * 16) * 1024 + (r & 7) * 128 + (k & 63) * 2);
        *reinterpret_cast<uint2*>(sAhi + sw) = make_uint2(pk2(h0, h1), pk2(h2, h3));
        *reinterpret_cast<uint2*>(sAlo + sw) = make_uint2(pk2(l0, l1), pk2(l2, l3));
    }

    const u64 aH = MAKE_SMEM_DESC(sbase + KV_AHI), aL = MAKE_SMEM_DESC(sbase + KV_ALO);
    const u64 b0H = MAKE_SMEM_DESC(sbase + KV_B0H), b0L = MAKE_SMEM_DESC(sbase + KV_B0L);
    const u64 b1H = MAKE_SMEM_DESC(sbase + KV_B1H), b1L = MAKE_SMEM_DESC(sbase + KV_B1L);

    const int rr = (wid & 3) * 32 + lane;
    const int cb = (wid >> 2) * 128;
    const int b  = blockIdx.x * 32 + (rr >> 2);

    int w0 = 0, w1 = 0, pend0 = 0, pend1 = 0;

    for (int m = 0; m < 4; ++m) {
        // phase 1: Q (cols 0-255) + K (cols 256-511)
        for (int t = 0; t < 16; ++t) {
            const int isK = t >> 3, nch = (t >> 2) & 1, kch = t & 3;
            const int buf = t & 1;
            if (buf == 0) { if (pend0) { MBARRIER_WAIT_PARITY(sbase + KV_MB0, w0 & 1); ++w0; pend0 = 0; } }
            else          { if (pend1) { MBARRIER_WAIT_PARITY(sbase + KV_MB1, w1 & 1); ++w1; pend1 = 0; } }
            {
                float4* dh = reinterpret_cast<float4*>(smA + (buf ? KV_B1H : KV_B0H));
                float4* dl = reinterpret_cast<float4*>(smA + (buf ? KV_B1L : KV_B0L));
                if (isK) {
                    const float4* s4 = reinterpret_cast<const float4*>(
                        g_wkt + (size_t)(((m * 2 + nch) * 4 + kch)) * 16384);
#pragma unroll
                    for (int i = 0; i < 4; ++i) {
                        dh[tid + i * 256] = s4[tid + i * 256];
                        dl[tid + i * 256] = s4[1024 + tid + i * 256];
                    }
                } else {
                    const float4* s4 = reinterpret_cast<const float4*>(
                        g_wqt + (size_t)(m * 4 + kch) * 32768);
#pragma unroll
                    for (int i = 0; i < 4; ++i) {
                        dh[tid + i * 256] = s4[nch * 1024 + tid + i * 256];
                        dl[tid + i * 256] = s4[2048 + nch * 1024 + tid + i * 256];
                    }
                }
            }
            __syncthreads();
            if (wid == 0) {
                asm volatile("fence.proxy.async.shared::cta;" ::: "memory");
                TCGEN05_FENCE_AFTER();
                if (elect_one_pred()) {
                    const u64 bH = buf ? b1H : b0H, bL = buf ? b1L : b0L;
                    const uint32_t dcol = tmem + isK * 256 + nch * 128;
#pragma unroll
                    for (int j = 0; j < 4; ++j) {
                        const u64 ao = (u64)(kch * 1024 + j * 2), bo = (u64)(j * 2);
                        mma_f16_ss(dcol, aH + ao, bH + bo, IDESC_BF16_M128_N128,
                                   (kch == 0 && j == 0) ? 0u : 1u);
                        mma_f16_ss(dcol, aH + ao, bL + bo, IDESC_BF16_M128_N128, 1u);
                        mma_f16_ss(dcol, aL + ao, bH + bo, IDESC_BF16_M128_N128, 1u);
                    }
                    TCGEN05_COMMIT(sbase + (buf ? KV_MB1 : KV_MB0));
                }
            }
            if (buf == 0) pend0 = 1; else pend1 = 1;
        }
        if (pend0) { MBARRIER_WAIT_PARITY(sbase + KV_MB0, w0 & 1); ++w0; pend0 = 0; }
        if (pend1) { MBARRIER_WAIT_PARITY(sbase + KV_MB1, w1 & 1); ++w1; pend1 = 0; }
        TCGEN05_FENCE_AFTER();

        // epi1: scores + softmax -> p[4]
        float p[4];
        const int qlane = (lane & ~3) + m;
        for (int cc = 0; cc < 4; ++cc) {
            const int dof = cb + cc * 32;
            uint32_t qr[32];
            TCGEN05_LD_32X32B_X32(qr, tmem + dof);
            TCGEN05_WAIT_LD();
            uint32_t kr[32];
            TCGEN05_LD_32X32B_X32(kr, tmem + 256 + dof);
            TCGEN05_WAIT_LD();
            const float* bqp = bq + m * 256 + dof;
            const float* bkp = bk + m * 256 + dof;
            float s = 0.f;
#pragma unroll
            for (int j = 0; j < 32; ++j) {
                const float qv = __shfl_sync(0xffffffffu, __uint_as_float(qr[j]), qlane)
                               + bqp[j] * 0.17677669529663687f;
                s = fmaf(qv, __uint_as_float(kr[j]) + bkp[j], s);
            }
            float mx = s;
            mx = fmaxf(mx, __shfl_xor_sync(0xffffffffu, mx, 1));
            mx = fmaxf(mx, __shfl_xor_sync(0xffffffffu, mx, 2));
            float e = expf(s - mx);
            float se = e;
            se += __shfl_xor_sync(0xffffffffu, se, 1);
            se += __shfl_xor_sync(0xffffffffu, se, 2);
            p[cc] = e / se;
        }
        TCGEN05_FENCE_BEFORE();
        __syncthreads();

        // phase 2: V (cols 0-255)
        for (int t = 0; t < 8; ++t) {
            const int nch = t >> 2, kch = t & 3;
            const int buf = t & 1;
            if (buf == 0) { if (pend0) { MBARRIER_WAIT_PARITY(sbase + KV_MB0, w0 & 1); ++w0; pend0 = 0; } }
            else          { if (pend1) { MBARRIER_WAIT_PARITY(sbase + KV_MB1, w1 & 1); ++w1; pend1 = 0; } }
            {
                const float4* s4 = reinterpret_cast<const float4*>(
                    g_wvt + (size_t)(((m * 2 + nch) * 4 + kch)) * 16384);
                float4* dh = reinterpret_cast<float4*>(smA + (buf ? KV_B1H : KV_B0H));
                float4* dl = reinterpret_cast<float4*>(smA + (buf ? KV_B1L : KV_B0L));
#pragma unroll
                for (int i = 0; i < 4; ++i) {
                    dh[tid + i * 256] = s4[tid + i * 256];
                    dl[tid + i * 256] = s4[1024 + tid + i * 256];
                }
            }
            __syncthreads();
            if (wid == 0) {
                asm volatile("fence.proxy.async.shared::cta;" ::: "memory");
                TCGEN05_FENCE_AFTER();
                if (elect_one_pred()) {
                    const u64 bH = buf ? b1H : b0H, bL = buf ? b1L : b0L;
                    const uint32_t dcol = tmem + nch * 128;
#pragma unroll
                    for (int j = 0; j < 4; ++j) {
                        const u64 ao = (u64)(kch * 1024 + j * 2), bo = (u64)(j * 2);
                        mma_f16_ss(dcol, aH + ao, bH + bo, IDESC_BF16_M128_N128,
                                   (kch == 0 && j == 0) ? 0u : 1u);
                        mma_f16_ss(dcol, aH + ao, bL + bo, IDESC_BF16_M128_N128, 1u);
                        mma_f16_ss(dcol, aL + ao, bH + bo, IDESC_BF16_M128_N128, 1u);
                    }
                    TCGEN05_COMMIT(sbase + (buf ? KV_MB1 : KV_MB0));
                }
            }
            if (buf == 0) pend0 = 1; else pend1 = 1;
        }
        if (pend0) { MBARRIER_WAIT_PARITY(sbase + KV_MB0, w0 & 1); ++w0; pend0 = 0; }
        if (pend1) { MBARRIER_WAIT_PARITY(sbase + KV_MB1, w1 & 1); ++w1; pend1 = 0; }
        TCGEN05_FENCE_AFTER();

        // epi2: Oh = sum p_n * v_n
        for (int cc = 0; cc < 4; ++cc) {
            const int dof = cb + cc * 32;
            uint32_t vr[32];
            TCGEN05_LD_32X32B_X32(vr, tmem + dof);
            TCGEN05_WAIT_LD();
            const float* bvp = bv + m * 256 + dof;
            float t32[32];
#pragma unroll
            for (int j = 0; j < 32; ++j)
                t32[j] = p[cc] * (__uint_as_float(vr[j]) + bvp[j]);
#pragma unroll
            for (int j = 0; j < 32; ++j) {
                t32[j] += __shfl_xor_sync(0xffffffffu, t32[j], 1);
                t32[j] += __shfl_xor_sync(0xffffffffu, t32[j], 2);
            }
            const int qi = lane & 3;
            float* op = g_oh + ((size_t)m * 32768 + b) * 256 + dof + qi * 8;
            *reinterpret_cast<float4*>(op) =
                make_float4(t32[qi * 8 + 0], t32[qi * 8 + 1], t32[qi * 8 + 2], t32[qi * 8 + 3]);
            *reinterpret_cast<float4*>(op + 4) =
                make_float4(t32[qi * 8 + 4], t32[qi * 8 + 5], t32[qi * 8 + 6], t32[qi * 8 + 7]);
        }
        TCGEN05_FENCE_BEFORE();
        __syncthreads();
    }

    if (tid == 0) {
        asm volatile("mbarrier.inval.shared.b64 [%0];" :: "r"(sbase + KV_MB0) : "memory");
        asm volatile("mbarrier.inval.shared.b64 [%0];" :: "r"(sbase + KV_MB1) : "memory");
    }
    __syncthreads();
    if (wid == 0) TCGEN05_DEALLOC(tmem, 512);

#else
    const int b = blockIdx.x * 32 + (tid >> 3);
    const int h = tid & 7;
    for (int m = 0; m < 4; ++m) {
        float q[32];
        for (int d = 0; d < 32; ++d) {
            float qd = bq[m * 256 + h * 32 + d] * 0.17677669529663687f;
            for (int k = 0; k < 256; ++k)
                qd = fmaf(x[(size_t)(b * 4 + m) * 256 + k], wrec256(g_wqt, m, h * 32 + d, k), qd);
            q[d] = qd;
        }
        float sc[4];
        for (int n = 0; n < 4; ++n) {
            float s = 0.f;
            for (int d = 0; d < 32; ++d) {
                float kd = bk[m * 256 + h * 32 + d];
                for (int k = 0; k < 256; ++k)
                    kd = fmaf(x[(size_t)(b * 4 + n) * 256 + k], wrec128(g_wkt, m, h * 32 + d, k), kd);
                s = fmaf(q[d], kd, s);
            }
            sc[n] = s;
        }
        const float mx = fmaxf(fmaxf(sc[0], sc[1]), fmaxf(sc[2], sc[3]));
        float e[4], se = 0.f;
        for (int n = 0; n < 4; ++n) { e[n] = expf(sc[n] - mx); se += e[n]; }
        for (int d = 0; d < 32; ++d) {
            float o = 0.f;
            for (int n = 0; n < 4; ++n) {
                float vd = bv[m * 256 + h * 32 + d];
                for (int k = 0; k < 256; ++k)
                    vd = fmaf(x[(size_t)(b * 4 + n) * 256 + k], wrec128(g_wvt, m, h * 32 + d, k), vd);
                o = fmaf(e[n] / se, vd, o);
            }
            g_oh[((size_t)m * 32768 + b) * 256 + h * 32 + d] = o;
        }
    }
#endif
}

// =====================================================================
// Kernel D: Wo projection + gate MLP + LayerNorm (fully fused)
// grid (256, 4), 256 threads
// Wo -> TMEM cols 0-255; gate1 = Oh·Wc + x·g1wx -> cols 256-319.
// =====================================================================
__global__ __launch_bounds__(256, 1)
void gcma_qo(const float* __restrict__ x, const float* __restrict__ bo,
             const float* __restrict__ g1w, const float* __restrict__ g1b,
             const float* __restrict__ g2w, const float* __restrict__ g2b,
             const float* __restrict__ lng, const float* __restrict__ lnb,
             float* __restrict__ out)
{
    extern __shared__ char smQ[];
    const int tid = threadIdx.x;
    const int m   = blockIdx.y;
    const int b0  = blockIdx.x * 128;

#if GB_TC
    const uint32_t sbase = smem_to_u32(smQ);
    const int wid = tid >> 5, lane = tid & 31;
    char* sAhi = smQ + KV_AHI;
    char* sAlo = smQ + KV_ALO;
    float* sGate = reinterpret_cast<float*>(smQ + KV_GATE);

    if (wid == 0) TCGEN05_ALLOC(sbase + 0, 512);
    if (tid == 0) { MBARRIER_INIT(sbase + KV_MB0, 1); MBARRIER_INIT(sbase + KV_MB1, 1); }
    __syncthreads();
    uint32_t tmem;
    asm volatile("ld.shared.b32 %0, [%1];" : "=r"(tmem) : "r"(sbase + 0));

    // stage Oh split into A region
    for (int idx = tid; idx < 8192; idx += 256) {
        const int r = idx >> 6, k = (idx & 63) << 2;
        const float4 v = *reinterpret_cast<const float4*>(
            g_oh + ((size_t)m * 32768 + b0 + r) * 256 + k);
        __nv_bfloat16 h0, h1, h2, h3, l0, l1, l2, l3;
        bsplit(v.x, h0, l0); bsplit(v.y, h1, l1);
        bsplit(v.z, h2, l2); bsplit(v.w, h3, l3);
        const uint32_t sw = swz128((uint32_t)((r >> 3) + (k >> 6) * 16) * 1024 + (r & 7) * 128 + (k & 63) * 2);
        *reinterpret_cast<uint2*>(sAhi + sw) = make_uint2(pk2(h0, h1), pk2(h2, h3));
        *reinterpret_cast<uint2*>(sAlo + sw) = make_uint2(pk2(l0, l1), pk2(l2, l3));
    }

    const u64 aH = MAKE_SMEM_DESC(sbase + KV_AHI), aL = MAKE_SMEM_DESC(sbase + KV_ALO);
    const u64 b0H = MAKE_SMEM_DESC(sbase + KV_B0H), b0L = MAKE_SMEM_DESC(sbase + KV_B0L);
    const u64 b1H = MAKE_SMEM_DESC(sbase + KV_B1H), b1L = MAKE_SMEM_DESC(sbase + KV_B1L);

    int w0 = 0, w1 = 0, pend0 = 0, pend1 = 0;

    // 12 pipelined chunks: 0-7 Wo (D cols 0-255), 8-11 Oh·Wc (D cols 256-319)
    for (int c = 0; c < 12; ++c) {
        const int isG = (c >= 8);
        const int nch = isG ? 0 : (c >> 2);
        const int kch = c & 3;
        const int buf = c & 1;
        if (buf == 0) { if (pend0) { MBARRIER_WAIT_PARITY(sbase + KV_MB0, w0 & 1); ++w0; pend0 = 0; } }
        else          { if (pend1) { MBARRIER_WAIT_PARITY(sbase + KV_MB1, w1 & 1); ++w1; pend1 = 0; } }
        {
            float4* dh = reinterpret_cast<float4*>(smQ + (buf ? KV_B1H : KV_B0H));
            float4* dl = reinterpret_cast<float4*>(smQ + (buf ? KV_B1L : KV_B0L));
            if (!isG) {
                const float4* s4 = reinterpret_cast<const float4*>(g_wot + (size_t)(m * 4 + kch) * 32768);
#pragma unroll
                for (int i = 0; i < 4; ++i) {
                    dh[tid + i * 256] = s4[nch * 1024 + tid + i * 256];
                    dl[tid + i * 256] = s4[2048 + nch * 1024 + tid + i * 256];
                }
            } else {
                const float4* s4 = reinterpret_cast<const float4*>(g_wct + (size_t)(m * 4 + kch) * 8192);
#pragma unroll
                for (int i = 0; i < 2; ++i) {
                    dh[tid + i * 256] = s4[tid + i * 256];
                    dl[tid + i * 256] = s4[512 + tid + i * 256];
                }
            }
        }
        __syncthreads();
        if (wid == 0) {
            asm volatile("fence.proxy.async.shared::cta;" ::: "memory");
            TCGEN05_FENCE_AFTER();
            if (elect_one_pred()) {
                const u64 bH = buf ? b1H : b0H, bL = buf ? b1L : b0L;
                const uint32_t dcol = isG ? (tmem + 256) : (tmem + nch * 128);
                const uint32_t idsc = isG ? IDESC_BF16_M128_N64 : IDESC_BF16_M128_N128;
#pragma unroll
                for (int j = 0; j < 4; ++j) {
                    const u64 ao = (u64)(kch * 1024 + j * 2), bo2 = (u64)(j * 2);
                    mma_f16_ss(dcol, aH + ao, bH + bo2, idsc, (kch == 0 && j == 0) ? 0u : 1u);
                    mma_f16_ss(dcol, aH + ao, bL + bo2, idsc, 1u);
                    mma_f16_ss(dcol, aL + ao, bH + bo2, idsc, 1u);
                }
                TCGEN05_COMMIT(sbase + (buf ? KV_MB1 : KV_MB0));
            }
        }
        if (buf == 0) pend0 = 1; else pend1 = 1;
    }
    if (pend0) { MBARRIER_WAIT_PARITY(sbase + KV_MB0, w0 & 1); ++w0; pend0 = 0; }
    if (pend1) { MBARRIER_WAIT_PARITY(sbase + KV_MB1, w1 & 1); ++w1; pend1 = 0; }
    TCGEN05_FENCE_AFTER();

    // x·g1wx: 4 serial K=64 chunks, accumulate into D cols 256-319
    const u64 xHd = b0H, xLd = b0L;
    const u64 wHd = b1H, wLd = MAKE_SMEM_DESC(sbase + KV_B1H + 8192);
    for (int kch = 0; kch < 4; ++kch) {
        // stage x quarter split into B0H/B0L (16KB each)
        for (int idx = tid; idx < 2048; idx += 256) {
            const int r = idx >> 4, k4 = (idx & 15) << 2;
            const float4 v = *reinterpret_cast<const float4*>(
                x + ((size_t)(b0 + r) * 4 + m) * 256 + kch * 64 + k4);
            __nv_bfloat16 h0, h1, h2, h3, l0, l1, l2, l3;
            bsplit(v.x, h0, l0); bsplit(v.y, h1, l1);
            bsplit(v.z, h2, l2); bsplit(v.w, h3, l3);
            const uint32_t sw = swz128((uint32_t)(r >> 3) * 1024 + (r & 7) * 128 + k4 * 2);
            *reinterpret_cast<uint2*>(smQ + KV_B0H + sw) = make_uint2(pk2(h0, h1), pk2(h2, h3));
            *reinterpret_cast<uint2*>(smQ + KV_B0L + sw) = make_uint2(pk2(l0, l1), pk2(l2, l3));
        }
        // stage g1wx tile (hi+lo 16KB contiguous) into B1H
        {
            const float4* s4 = reinterpret_cast<const float4*>(g_wxt + (size_t)(m * 4 + kch) * 8192);
            float4* d4 = reinterpret_cast<float4*>(smQ + KV_B1H);
#pragma unroll
            for (int i = 0; i < 4; ++i) d4[tid + i * 256] = s4[tid + i * 256];
        }
        __syncthreads();
        if (wid == 0) {
            asm volatile("fence.proxy.async.shared::cta;" ::: "memory");
            TCGEN05_FENCE_AFTER();
            if (elect_one_pred()) {
#pragma unroll
                for (int j = 0; j < 4; ++j) {
                    const u64 ao = (u64)(j * 2), bo2 = (u64)(j * 2);
                    mma_f16_ss(tmem + 256, xHd + ao, wHd + bo2, IDESC_BF16_M128_N64, 1u);
                    mma_f16_ss(tmem + 256, xHd + ao, wLd + bo2, IDESC_BF16_M128_N64, 1u);
                    mma_f16_ss(tmem + 256, xLd + ao, wHd + bo2, IDESC_BF16_M128_N64, 1u);
                }
                TCGEN05_COMMIT(sbase + KV_MB0);
            }
        }
        MBARRIER_WAIT_PARITY(sbase + KV_MB0, w0 & 1);
        ++w0;
        TCGEN05_FENCE_AFTER();
        __syncthreads();
    }

    // ---- AO epilogue: TMEM cols 0-255 + bo -> fp32 into A region ----
    float* aFP = reinterpret_cast<float*>(smQ + KV_AHI);
    {
        const int rr = (wid & 3) * 32 + lane;
        const int cbl = (wid >> 2) * 128;
        for (int cc = 0; cc < 4; ++cc) {
            uint32_t dr[32];
            TCGEN05_LD_32X32B_X32(dr, tmem + cbl + cc * 32);
            TCGEN05_WAIT_LD();
            const int c0 = cbl + cc * 32;
#pragma unroll
            for (int j = 0; j < 32; ++j)
                aFP[rr * 256 + c0 + j] = __uint_as_float(dr[j]) + bo[m * 256 + c0 + j];
        }
    }

    // ---- gate epilogue: cols 256-319 -> tanh -> gate2 -> sigmoid ----
    if (wid < 4) {
        const int rr2 = wid * 32 + lane;
        uint32_t ga[32], gb2[32];
        TCGEN05_LD_32X32B_X32(ga, tmem + 256);
        TCGEN05_WAIT_LD();
        TCGEN05_LD_32X32B_X32(gb2, tmem + 288);
        TCGEN05_WAIT_LD();
        float dot = g2b[m];
#pragma unroll
        for (int j = 0; j < 32; ++j)
            dot = fmaf(tanhf(__uint_as_float(ga[j]) + g_bc[m * 64 + j]), g2w[m * 64 + j], dot);
#pragma unroll
        for (int j = 0; j < 32; ++j)
            dot = fmaf(tanhf(__uint_as_float(gb2[j]) + g_bc[m * 64 + 32 + j]), g2w[m * 64 + 32 + j], dot);
        const float gate = 1.f / (1.f + expf(-dot));
        sGate[rr2] = gate;
        out[OUT_GATE_BASE + (size_t)(b0 + rr2) * 4 + m] = gate;
    }
    TCGEN05_FENCE_BEFORE();
    __syncthreads();

    // ---- LayerNorm: 16 rows per warp ----
    {
#pragma unroll 1
        for (int i = 0; i < 16; ++i) {
            const int bl = wid * 16 + i;
            const float* xr  = x + ((size_t)(b0 + bl) * 4 + m) * 256;
            const float* aor = aFP + bl * 256;
            const float gate = sGate[bl];
            float r[8];
            float sum = 0.f;
#pragma unroll
            for (int k = 0; k < 8; ++k) {
                const int d = k * 32 + lane;
                r[k] = xr[d] + gate * aor[d];
                sum += r[k];
            }
#pragma unroll
            for (int o = 16; o; o >>= 1) sum += __shfl_xor_sync(0xffffffffu, sum, o);
            const float mu = sum * (1.f / 256.f);
            float var = 0.f;
#pragma unroll
            for (int k = 0; k < 8; ++k) { const float t = r[k] - mu; var = fmaf(t, t, var); }
#pragma unroll
            for (int o = 16; o; o >>= 1) var += __shfl_xor_sync(0xffffffffu, var, o);
            const float rs = rsqrtf(var * (1.f / 256.f) + 1e-5f);
            float* yr = g_y + ((size_t)(b0 + bl) * 4 + m) * 256;
#pragma unroll
            for (int k = 0; k < 8; ++k) {
                const int d = k * 32 + lane;
                yr[d] = (r[k] - mu) * rs * lng[m * 256 + d] + lnb[m * 256 + d];
            }
        }
    }

    __syncthreads();
    if (tid == 0) {
        asm volatile("mbarrier.inval.shared.b64 [%0];" :: "r"(sbase + KV_MB0) : "memory");
        asm volatile("mbarrier.inval.shared.b64 [%0];" :: "r"(sbase + KV_MB1) : "memory");
    }
    __syncthreads();
    if (wid == 0) TCGEN05_DEALLOC(tmem, 512);

#else
    // fp32 fallback: AO -> g_ao, then gate + LN (slow; never runs on sm_103a)
    for (int e = tid; e < 128 * 256; e += 256) {
        const int r = e >> 8, n = e & 255;
        float dot = 0.f;
        for (int k = 0; k < 256; ++k)
            dot = fmaf(g_oh[((size_t)m * 32768 + b0 + r) * 256 + k], wrec256(g_wot, m, n, k), dot);
        g_ao[((size_t)m * 32768 + b0 + r) * 256 + n] = dot + bo[m * 256 + n];
    }
    __syncthreads();
    if (tid < 128) {
        const int b = b0 + tid;
        const float* xr  = x + ((size_t)b * 4 + m) * 256;
        const float* aor = g_ao + ((size_t)m * 32768 + b) * 256;
        float dot2 = g2b[m];
        for (int h = 0; h < 64; ++h) {
            float s = g1b[m * 64 + h];
            for (int k = 0; k < 256; ++k) {
                s = fmaf(xr[k],  g1w[(size_t)m * 32768 + h * 512 + k], s);
                s = fmaf(aor[k], g1w[(size_t)m * 32768 + h * 512 + 256 + k], s);
            }
            dot2 = fmaf(tanhf(s), g2w[m * 64 + h], dot2);
        }
        const float gate = 1.f / (1.f + expf(-dot2));
        out[OUT_GATE_BASE + (size_t)b * 4 + m] = gate;
        float sum = 0.f;
        for (int d = 0; d < 256; ++d) sum += xr[d] + gate * aor[d];
        const float mu = sum / 256.f;
        float var = 0.f;
        for (int d = 0; d < 256; ++d) {
            const float t = xr[d] + gate * aor[d] - mu;
            var = fmaf(t, t, var);
        }
        const float rs = rsqrtf(var / 256.f + 1e-5f);
        float* yr = g_y + ((size_t)b * 4 + m) * 256;
        for (int d = 0; d < 256; ++d)
            yr[d] = (xr[d] + gate * aor[d] - mu) * rs * lng[m * 256 + d] + lnb[m * 256 + d];
    }
#endif
}

// =====================================================================
// Kernel F: FF (tcgen05)
// =====================================================================
#define P2_SMEM 197632
#define P2_TM    0
#define P2_MB    8
#define P2_AHI   1024
#define P2_ALO   66560
#define P2_BHI   132096
#define P2_BLO   164864

static __device__ __forceinline__ void loadB(const __nv_bfloat16* base, int m, int c1, int c2,
                                             float4 pf[16], int tid) {
    const float4* src = reinterpret_cast<const float4*>(base + (size_t)((m * 4 + c1) * 4 + c2) * 32768);
#pragma unroll
    for (int i = 0; i < 8; ++i) {
        pf[i]     = src[tid + i * 256];
        pf[8 + i] = src[2048 + tid + i * 256];
    }
}
static __device__ __forceinline__ void stsB(char* sBhi, char* sBlo, const float4 pf[16], int tid) {
#pragma unroll
    for (int i = 0; i < 8; ++i) {
        reinterpret_cast<float4*>(sBhi)[tid + i * 256] = pf[i];
        reinterpret_cast<float4*>(sBlo)[tid + i * 256] = pf[8 + i];
    }
}

__global__ __launch_bounds__(256, 1)
void gcma_part2tc(const float* __restrict__ f1w, const float* __restrict__ f1b,
                  const float* __restrict__ f2w, const float* __restrict__ f2b,
                  float* __restrict__ out)
{
    extern __shared__ char sm2[];
    const int tid  = threadIdx.x;
    const int m    = blockIdx.y;
    const int b0   = blockIdx.x * 128;

#if GB_TC
    const uint32_t sbase = smem_to_u32(sm2);
    const uint32_t TMP  = sbase + P2_TM;
    const uint32_t MBAR = sbase + P2_MB;
    char* sAhi = sm2 + P2_AHI;
    char* sAlo = sm2 + P2_ALO;
    char* sBhi = sm2 + P2_BHI;
    char* sBlo = sm2 + P2_BLO;
    const uint32_t aHiA = sbase + P2_AHI, aLoA = sbase + P2_ALO;
    const uint32_t bHiA = sbase + P2_BHI, bLoA = sbase + P2_BLO;

    const int wid  = tid >> 5, lane = tid & 31;
    unsigned* hfbase = g_hfscr + (size_t)(blockIdx.y * 256 + blockIdx.x) * 131072u;

    if (wid == 0) TCGEN05_ALLOC(TMP, 512);
    if (tid == 0) MBARRIER_INIT(MBAR, 1);
    __syncthreads();
    uint32_t tmem;
    asm volatile("ld.shared.b32 %0, [%1];" : "=r"(tmem) : "r"(TMP));

    for (int idx = tid; idx < 8192; idx += 256) {
        const int r = idx >> 6, k = (idx & 63) << 2;
        const float4 v = *reinterpret_cast<const float4*>(
            g_y + ((size_t)(b0 + r) * 4 + m) * 256 + k);
        __nv_bfloat16 h0, h1, h2, h3, l0, l1, l2, l3;
        bsplit(v.x, h0, l0); bsplit(v.y, h1, l1);
        bsplit(v.z, h2, l2); bsplit(v.w, h3, l3);
        const uint32_t sw = swz128((uint32_t)((r >> 3) + (k >> 6) * 16) * 1024 + (r & 7) * 128 + (k & 63) * 2);
        *reinterpret_cast<uint2*>(sAhi + sw) = make_uint2(pk2(h0, h1), pk2(h2, h3));
        *reinterpret_cast<uint2*>(sAlo + sw) = make_uint2(pk2(l0, l1), pk2(l2, l3));
    }

    float4 pf[16];
    loadB(g_w1t, m, 0, 0, pf, tid);
    int ph = 0;
    const u64 aH = MAKE_SMEM_DESC(aHiA), aL = MAKE_SMEM_DESC(aLoA);
    const u64 bH = MAKE_SMEM_DESC(bHiA), bL = MAKE_SMEM_DESC(bLoA);

    for (int nch = 0; nch < 4; ++nch) {
        for (int kch = 0; kch < 4; ++kch) {
            stsB(sBhi, sBlo, pf, tid);
            __syncthreads();
            if (wid == 0) {
                asm volatile("fence.proxy.async.shared::cta;" ::: "memory");
                TCGEN05_FENCE_AFTER();
                if (elect_one_pred()) {
#pragma unroll
                    for (int j = 0; j < 4; ++j) {
                        const u64 ao = (u64)(kch * 1024 + j * 2), bo = (u64)(j * 2);
                        mma_f16_ss(tmem, aH + ao, bH + bo, IDESC_BF16_M128_N256,
                                   (kch == 0 && j == 0) ? 0u : 1u);
                        mma_f16_ss(tmem, aH + ao, bL + bo, IDESC_BF16_M128_N256, 1u);
                        mma_f16_ss(tmem, aL + ao, bH + bo, IDESC_BF16_M128_N256, 1u);
                    }
                    TCGEN05_COMMIT(MBAR);
                }
            }
            const int nb = nch * 4 + kch + 1;
            if (nb < 16) loadB(g_w1t, m, nb >> 2, nb & 3, pf, tid);
            else         loadB(g_w2t, m, 0, 0, pf, tid);
            MBARRIER_WAIT_PARITY(MBAR, ph & 1);
            ++ph;
            TCGEN05_FENCE_AFTER();
        }
        {
            const int r  = (wid & 3) * 32 + lane;
            const int cb = (wid >> 2) * 128;
            for (int cc = 0; cc < 4; ++cc) {
                uint32_t dr[32];
                TCGEN05_LD_32X32B_X32(dr, tmem + cb + cc * 32);
                TCGEN05_WAIT_LD();
                TCGEN05_FENCE_BEFORE();
                const int c0 = nch * 256 + cb + cc * 32;
                unsigned* dst = hfbase + (size_t)r * 1024 + c0;
#pragma unroll
                for (int j = 0; j < 32; ++j) {
                    float v = __uint_as_float(dr[j]) + f1b[m * 1024 + c0 + j];
                    v = 0.5f * v * (1.f + erff(v * 0.7071067811865476f));
                    __nv_bfloat16 h, l;
                    bsplit(v, h, l);
                    dst[j] = pk2(h, l);
                }
            }
        }
        __syncthreads();
    }

    for (int ch = 0; ch < 4; ++ch) {
        for (int idx = tid; idx < 8192; idx += 256) {
            const int r = idx >> 6, k = (idx & 63) << 2;
            const uint4 u = *reinterpret_cast<const uint4*>(
                hfbase + (size_t)r * 1024 + ch * 256 + k);
            const unsigned uu[4] = {u.x, u.y, u.z, u.w};
            __nv_bfloat16 h[4], l[4];
#pragma unroll
            for (int j = 0; j < 4; ++j) {
                h[j] = __ushort_as_bfloat16((unsigned short)(uu[j] & 0xFFFFu));
                l[j] = __ushort_as_bfloat16((unsigned short)(uu[j] >> 16));
            }
            const uint32_t sw = swz128((uint32_t)((r >> 3) + (k >> 6) * 16) * 1024 + (r & 7) * 128 + (k & 63) * 2);
            *reinterpret_cast<uint2*>(sAhi + sw) = make_uint2(pk2(h[0], h[1]), pk2(h[2], h[3]));
            *reinterpret_cast<uint2*>(sAlo + sw) = make_uint2(pk2(l[0], l[1]), pk2(l[2], l[3]));
        }
        for (int kc = 0; kc < 4; ++kc) {
            stsB(sBhi, sBlo, pf, tid);
            __syncthreads();
            if (wid == 0) {
                asm volatile("fence.proxy.async.shared::cta;" ::: "memory");
                TCGEN05_FENCE_AFTER();
                if (elect_one_pred()) {
#pragma unroll
                    for (int j = 0; j < 4; ++j) {
                        const u64 ao = (u64)(kc * 1024 + j * 2), bo = (u64)(j * 2);
                        mma_f16_ss(tmem + 256, aH + ao, bH + bo, IDESC_BF16_M128_N256,
                                   (ch == 0 && kc == 0 && j == 0) ? 0u : 1u);
                        mma_f16_ss(tmem + 256, aH + ao, bL + bo, IDESC_BF16_M128_N256, 1u);
                        mma_f16_ss(tmem + 256, aL + ao, bH + bo, IDESC_BF16_M128_N256, 1u);
                    }
                    TCGEN05_COMMIT(MBAR);
                }
            }
            const int nb = ch * 4 + kc + 1;
            if (nb < 16) loadB(g_w2t, m, nb >> 2, nb & 3, pf, tid);
            MBARRIER_WAIT_PARITY(MBAR, ph & 1);
            ++ph;
            TCGEN05_FENCE_AFTER();
        }
    }

    {
        const int r  = (wid & 3) * 32 + lane;
        const int cb = (wid >> 2) * 128;
        for (int cc = 0; cc < 4; ++cc) {
            uint32_t dr[32];
            TCGEN05_LD_32X32B_X32(dr, tmem + 256 + cb + cc * 32);
            TCGEN05_WAIT_LD();
            TCGEN05_FENCE_BEFORE();
            const int c0 = cb + cc * 32;
            const float* yrow = g_y + ((size_t)(b0 + r) * 4 + m) * 256 + c0;
            float* orow = out + ((size_t)(b0 + r) * 4 + m) * 256 + c0;
#pragma unroll
            for (int j = 0; j < 32; ++j)
                orow[j] = yrow[j] + __uint_as_float(dr[j]) + f2b[m * 256 + c0 + j];
        }
    }

    __syncthreads();
    if (tid == 0)
        asm volatile("mbarrier.inval.shared.b64 [%0];" :: "r"(MBAR) : "memory");
    __syncthreads();
    if (wid == 0) TCGEN05_DEALLOC(tmem, 512);

#else
    // fp32 fallback: direct per-element FF (slow; never runs on sm_103a)
    for (int e = tid; e < 128 * 256; e += 256) {
        const int r = e >> 8, d = e & 255;
        const float* yr = g_y + ((size_t)(b0 + r) * 4 + m) * 256;
        float acc = f2b[m * 256 + d];
        for (int h = 0; h < 1024; ++h) {
            float v = f1b[m * 1024 + h];
            for (int k = 0; k < 256; ++k)
                v = fmaf(yr[k], f1w[(size_t)m * 262144 + (size_t)h * 256 + k], v);
            v = 0.5f * v * (1.f + erff(v * 0.7071067811865476f));
            acc = fmaf(v, f2w[(size_t)m * 262144 + (size_t)d * 1024 + h], acc);
        }
        out[((size_t)(b0 + r) * 4 + m) * 256 + d] = yr[d] + acc;
    }
#endif
}

extern "C" void kernel_launch(void* const* d_in, const int* in_sizes, int n_in,
                              void* d_out, int out_size) {
    const float* x   = (const float*)d_in[0];
    const float* Wq  = (const float*)d_in[1];
    const float* bq  = (const float*)d_in[2];
    const float* Wk  = (const float*)d_in[3];
    const float* bk  = (const float*)d_in[4];
    const float* Wv  = (const float*)d_in[5];
    const float* bv  = (const float*)d_in[6];
    const float* Wo  = (const float*)d_in[7];
    const float* bo  = (const float*)d_in[8];
    const float* g1w = (const float*)d_in[9];
    const float* g1b = (const float*)d_in[10];
    const float* g2w = (const float*)d_in[11];
    const float* g2b = (const float*)d_in[12];
    const float* lng = (const float*)d_in[13];
    const float* lnb = (const float*)d_in[14];
    const float* f1w = (const float*)d_in[15];
    const float* f1b = (const float*)d_in[16];
    const float* f2w = (const float*)d_in[17];
    const float* f2b = (const float*)d_in[18];
    float* out = (float*)d_out;

    cudaFuncSetAttribute(gcma_kvattn, cudaFuncAttributeMaxDynamicSharedMemorySize, KV_SMEM);
    cudaFuncSetAttribute(gcma_qo, cudaFuncAttributeMaxDynamicSharedMemorySize, KV_SMEM);
    cudaFuncSetAttribute(gcma_part2tc, cudaFuncAttributeMaxDynamicSharedMemorySize, P2_SMEM);

    conv_w_kernel<<<12288, 256>>>(f1w, f2w, Wk, Wv, Wq, Wo);
    gcma_wc<<<16, 256>>>(Wo, bo, g1w, g1b);
    gcma_kvattn<<<1024, 256, KV_SMEM>>>(x, bq, bk, bv);
    gcma_qo<<<dim3(256, 4), 256, KV_SMEM>>>(x, bo, g1w, g1b, g2w, g2b, lng, lnb, out);
    gcma_part2tc<<<dim3(256, 4), 256, P2_SMEM>>>(f1w, f1b, f2w, f2b, out);
}